// round 16
// baseline (speedup 1.0000x reference)
#include <cuda_runtime.h>

#define HB 40
#define WB 40
#define HWB 1600          // 40*40
#define CIN 256
#define CMID 64
#define CENC 100
#define NBATCH 2

// Scratch (device globals; no allocation allowed)
__device__ float g_comp[NBATCH * CMID * HWB];   // (b,64,40,40)
__device__ float g_enc[NBATCH * CENC * HWB];    // (b,100,40,40)
__device__ float g_wgt[NBATCH * HWB * 100];     // softmaxed weights [b][p][k*4+d]

typedef unsigned long long u64;

// ---- packed fp32x2 helpers (sm_103a FFMA2 via PTX) ----
__device__ __forceinline__ u64 pack2(float x, float y) {
    u64 r; asm("mov.b64 %0, {%1, %2};" : "=l"(r) : "f"(x), "f"(y)); return r;
}
__device__ __forceinline__ void ffma2(u64 &d, u64 a, u64 b) {
    asm("fma.rn.f32x2 %0, %1, %2, %0;" : "+l"(d) : "l"(a), "l"(b));
}
__device__ __forceinline__ float2 unpack2(u64 v) {
    float2 f; asm("mov.b64 {%0, %1}, %2;" : "=f"(f.x), "=f"(f.y) : "l"(v)); return f;
}

// ---------------------------------------------------------------------------
// K1: 1x1 conv, ci-split x8 inside the block (deterministic smem reduce).
// Block = 640 threads = 80 px * 8 ci-splits; thread: 32 ci, 8 co (4 FFMA2/ci).
// (R14 version, verbatim — 12.2us measured.)
// ---------------------------------------------------------------------------
__global__ __launch_bounds__(640) void k1_compress(
    const float* __restrict__ x, const float* __restrict__ wcomp)
{
    __shared__ __align__(16) float ws[CIN * 8];   // [ci][co(8)]
    __shared__ __align__(16) u64 red[7 * 80 * 4]; // splits 1..7 partials

    const int tid   = threadIdx.x;
    const int px    = tid % 80;
    const int split = tid / 80;                   // 0..7
    const int p     = blockIdx.x * 80 + px;       // 20*80 = 1600 = HWB
    const int co0   = blockIdx.y * 8;
    const int b     = blockIdx.z;

    for (int i = tid; i < CIN * 8; i += 640) {
        int co = i >> 8, ci = i & 255;            // coalesced read in ci
        ws[ci * 8 + co] = wcomp[(co0 + co) * CIN + ci];
    }
    __syncthreads();

    const int ci0 = split * 32;
    const float* xb = x + (size_t)(b * CIN + ci0) * HWB + p;
    u64 acc0 = 0, acc1 = 0, acc2 = 0, acc3 = 0;   // (0.f,0.f)

    #pragma unroll 16
    for (int ci = 0; ci < 32; ++ci) {
        float xv = xb[(size_t)ci * HWB];
        u64 xx = pack2(xv, xv);
        const u64* wr = (const u64*)&ws[(ci0 + ci) * 8];  // broadcast LDS.64
        ffma2(acc0, xx, wr[0]);
        ffma2(acc1, xx, wr[1]);
        ffma2(acc2, xx, wr[2]);
        ffma2(acc3, xx, wr[3]);
    }

    if (split > 0) {
        u64* r = &red[((split - 1) * 80 + px) * 4];
        r[0] = acc0; r[1] = acc1; r[2] = acc2; r[3] = acc3;
    }
    __syncthreads();

    if (split == 0) {
        const u64 one = pack2(1.f, 1.f);
        #pragma unroll
        for (int s = 0; s < 7; ++s) {
            const u64* r = &red[(s * 80 + px) * 4];
            ffma2(acc0, one, r[0]);
            ffma2(acc1, one, r[1]);
            ffma2(acc2, one, r[2]);
            ffma2(acc3, one, r[3]);
        }
        float* ob = g_comp + (size_t)(b * CMID + co0) * HWB + p;
        float2 v;
        v = unpack2(acc0); ob[0 * HWB] = v.x; ob[1 * HWB] = v.y;
        v = unpack2(acc1); ob[2 * HWB] = v.x; ob[3 * HWB] = v.y;
        v = unpack2(acc2); ob[4 * HWB] = v.x; ob[5 * HWB] = v.y;
        v = unpack2(acc3); ob[6 * HWB] = v.x; ob[7 * HWB] = v.y;
    }
}

// ---------------------------------------------------------------------------
// K2: 3x3 conv 64->100, pad 1. (R14 version, verbatim.)
// ---------------------------------------------------------------------------
__global__ __launch_bounds__(128) void k2_encoder(const float* __restrict__ wenc)
{
    // xs2: 32 ci * 130 u64 = 4160 u64 (33.3KB) | ws: 288*10 floats (11.5KB)
    __shared__ __align__(16) float smem_all[4160 * 2 + 2880];   // 44.8KB
    u64*   xs2 = (u64*)smem_all;
    float* ws  = smem_all + 4160 * 2;

    const int tile = blockIdx.x;                  // 0..24
    const int co0  = blockIdx.y * 10;
    const int b    = blockIdx.z;
    const int h0 = (tile / 5) * 8, w0 = (tile % 5) * 8;
    const int tid = threadIdx.x;

    const int pxg   = tid & 15;                   // 16 groups of 4 px
    const int split = tid >> 4;                   // 0..7
    const int row   = pxg >> 1;                   // 0..7
    const int col0  = (pxg & 1) * 4;              // 0 or 4

    u64 acc[5][4];
    #pragma unroll
    for (int j = 0; j < 5; ++j)
        #pragma unroll
        for (int q = 0; q < 4; ++q) acc[j][q] = 0;

    #pragma unroll
    for (int phase = 0; phase < 2; ++phase) {
        if (phase) __syncthreads();               // phase-0 reads complete
        for (int i = tid; i < 3200; i += 128) {
            int ci_l = i / 100, r = i - ci_l * 100;
            int hh = r / 10, ww = r - hh * 10;
            int gh = h0 - 1 + hh, gw = w0 - 1 + ww;
            float v = 0.f;
            if ((unsigned)gh < (unsigned)HB && (unsigned)gw < (unsigned)WB)
                v = g_comp[(b * CMID + phase * 32 + ci_l) * HWB + gh * WB + gw];
            xs2[ci_l * 130 + hh * 13 + ww] = pack2(v, v);
        }
        for (int i = tid; i < 2880; i += 128) {
            int c = i / 288, il = i - c * 288;    // coalesced in il
            ws[il * 10 + c] = wenc[(co0 + c) * 576 + phase * 288 + il];
        }
        __syncthreads();

        #pragma unroll
        for (int q4 = 0; q4 < 4; ++q4) {
            const int ci_l = split * 4 + q4;      // 0..31 within phase
            const u64*  xrow = xs2 + ci_l * 130 + row * 13 + col0;
            const float* wb  = &ws[ci_l * 90];
            #pragma unroll
            for (int tr = 0; tr < 3; ++tr)
            #pragma unroll
            for (int tc = 0; tc < 3; ++tc) {
                const u64* xr = xrow + tr * 13 + tc;
                u64 xx0 = xr[0], xx1 = xr[1], xx2 = xr[2], xx3 = xr[3];
                const u64* wp = (const u64*)(wb + (tr * 3 + tc) * 10);
                #pragma unroll
                for (int j = 0; j < 5; ++j) {
                    u64 w = wp[j];
                    ffma2(acc[j][0], xx0, w);
                    ffma2(acc[j][1], xx1, w);
                    ffma2(acc[j][2], xx2, w);
                    ffma2(acc[j][3], xx3, w);
                }
            }
        }
    }

    __syncthreads();                              // all smem reads complete
    u64* red = (u64*)smem_all;                    // 7*16*20 u64 = 17.9KB
    if (split > 0) {
        u64* r = &red[((split - 1) * 16 + pxg) * 20];
        #pragma unroll
        for (int j = 0; j < 5; ++j)
            #pragma unroll
            for (int q = 0; q < 4; ++q) r[j * 4 + q] = acc[j][q];
    }
    __syncthreads();
    if (split == 0) {
        const u64 one = pack2(1.f, 1.f);
        #pragma unroll
        for (int s = 0; s < 7; ++s) {
            const u64* r = &red[(s * 16 + pxg) * 20];
            #pragma unroll
            for (int j = 0; j < 5; ++j)
                #pragma unroll
                for (int q = 0; q < 4; ++q) ffma2(acc[j][q], one, r[j * 4 + q]);
        }
        #pragma unroll
        for (int q = 0; q < 4; ++q) {
            const int sp = (h0 + row) * WB + (w0 + col0 + q);
            float* ob = g_enc + (size_t)(b * CENC + co0) * HWB + sp;
            #pragma unroll
            for (int j = 0; j < 5; ++j) {
                float2 v = unpack2(acc[j][q]);
                ob[(2 * j)     * HWB] = v.x;
                ob[(2 * j + 1) * HWB] = v.y;
            }
        }
    }
}

// ---------------------------------------------------------------------------
// K_wgt: softmax precompute, once per (b,p,d). Weight quirk (verified):
// t2=2*pw+d/2; si=t2/40; wc=t2%40; sj=d&1; logit_k = enc[b,k*4+si*2+sj,ph,wc].
// Output layout g_wgt[(b*HWB+p)*100 + k*4 + d] (K3 reads pairs as u64).
// grid 50 x 256 = 12800 threads = 2*1600*4.
// ---------------------------------------------------------------------------
__global__ __launch_bounds__(256) void k_wgt()
{
    const int g = blockIdx.x * 256 + threadIdx.x;     // 0..12799
    const int b = g / 6400;
    const int r = g - b * 6400;
    const int p = r >> 2;
    const int d = r & 3;
    const int ph = p / WB, pw = p % WB;
    const int t2 = 2 * pw + (d >> 1);
    const int si = (t2 >= WB) ? 1 : 0;
    const int wc = t2 - WB * si;
    const int sj = d & 1;
    const float* ebase = g_enc + (size_t)(b * CENC + si * 2 + sj) * HWB + ph * WB + wc;

    float v[25];
    #pragma unroll
    for (int k = 0; k < 25; ++k) v[k] = ebase[(size_t)k * 4 * HWB];
    float m = v[0];
    #pragma unroll
    for (int k = 1; k < 25; ++k) m = fmaxf(m, v[k]);
    float s = 0.f;
    #pragma unroll
    for (int k = 0; k < 25; ++k) { v[k] = __expf(v[k] - m); s += v[k]; }
    float inv = 1.f / s;
    float* ob = g_wgt + (size_t)(b * HWB + p) * 100 + d;
    #pragma unroll
    for (int k = 0; k < 25; ++k) ob[k * 4] = v[k] * inv;
}

// ---------------------------------------------------------------------------
// K3: reassembly. Weights staged coalesced (float4) from g_wgt into smem
// (same wsm layout as before), register-cached as u64 pairs. Inner loop
// split: interior pixels (ph,pw in [2,37]) skip all bounds masking.
// grid (50, 4, 2) x 256 threads.
// ---------------------------------------------------------------------------
__global__ __launch_bounds__(256) void k3_reassemble(
    const float* __restrict__ x, float* __restrict__ out)
{
    __shared__ __align__(16) float wsm[32 * 104];     // [pl][k*4+d], stride 104

    const int p0 = blockIdx.x * 32;
    const int c0 = blockIdx.y * 64;
    const int b  = blockIdx.z;
    const int tid = threadIdx.x;

    // coalesced weight stage: 32 px * 100 floats = 800 float4
    const float4* src = (const float4*)(g_wgt + (size_t)(b * HWB + p0) * 100);
    for (int i = tid; i < 800; i += 256) {
        int e = i << 2;
        int pl = e / 100, j = e - pl * 100;           // j % 4 == 0
        *(float4*)&wsm[pl * 104 + j] = src[i];
    }
    __syncthreads();

    const int pl = tid & 31, cq = tid >> 5;           // cq 0..7
    const int p  = p0 + pl;
    const int ph = p / WB, pw = p % WB;

    u64 wrA[25], wrB[25];                             // (d0,d1) / (d2,d3)
    #pragma unroll
    for (int k = 0; k < 25; ++k) {
        wrA[k] = *(const u64*)&wsm[pl * 104 + k * 4];
        wrB[k] = *(const u64*)&wsm[pl * 104 + k * 4 + 2];
    }

    const bool interior = (unsigned)(ph - 2) < 36u && (unsigned)(pw - 2) < 36u;

    if (interior) {
        for (int it = 0; it < 8; ++it) {
            const int c = c0 + cq + (it << 3);
            const float* xb = x + (size_t)(b * CIN + c) * HWB + p;
            u64 accA = 0, accB = 0;
            #pragma unroll
            for (int k = 0; k < 25; ++k) {
                float xv = __ldg(xb + (k / 5 - 2) * WB + (k % 5 - 2));
                u64 xx = pack2(xv, xv);
                ffma2(accA, xx, wrA[k]);
                ffma2(accB, xx, wrB[k]);
            }
            float2 a = unpack2(accA), bb = unpack2(accB);
            *reinterpret_cast<float4*>(out + (size_t)(b * CIN + c) * (HWB * 4) + 4 * p)
                = make_float4(a.x, a.y, bb.x, bb.y);
        }
    } else {
        unsigned mask = 0;
        #pragma unroll
        for (int k = 0; k < 25; ++k) {
            int di = k / 5 - 2, dj = k % 5 - 2;
            if ((unsigned)(ph + di) < (unsigned)HB && (unsigned)(pw + dj) < (unsigned)WB)
                mask |= 1u << k;
        }
        for (int it = 0; it < 8; ++it) {
            const int c = c0 + cq + (it << 3);
            const float* xb = x + (size_t)(b * CIN + c) * HWB + p;
            u64 accA = 0, accB = 0;
            #pragma unroll
            for (int k = 0; k < 25; ++k) {
                float xv = 0.f;
                if (mask & (1u << k))
                    xv = __ldg(xb + (k / 5 - 2) * WB + (k % 5 - 2));
                u64 xx = pack2(xv, xv);
                ffma2(accA, xx, wrA[k]);
                ffma2(accB, xx, wrB[k]);
            }
            float2 a = unpack2(accA), bb = unpack2(accB);
            *reinterpret_cast<float4*>(out + (size_t)(b * CIN + c) * (HWB * 4) + 4 * p)
                = make_float4(a.x, a.y, bb.x, bb.y);
        }
    }
}

// ---------------------------------------------------------------------------
extern "C" void kernel_launch(void* const* d_in, const int* in_sizes, int n_in,
                              void* d_out, int out_size)
{
    const float* x      = (const float*)d_in[0];   // (2,256,40,40)
    const float* w_comp = (const float*)d_in[1];   // (64,256,1,1)
    const float* w_enc  = (const float*)d_in[2];   // (100,64,3,3)
    float* out = (float*)d_out;                    // (2,256,80,80)

    k1_compress  <<<dim3(20, 8, 2),  640>>>(x, w_comp);
    k2_encoder   <<<dim3(25, 10, 2), 128>>>(w_enc);
    k_wgt        <<<50, 256>>>();
    k3_reassemble<<<dim3(50, 4, 2),  256>>>(x, out);
}